// round 10
// baseline (speedup 1.0000x reference)
#include <cuda_runtime.h>
#include <cuda_fp16.h>
#include <mma.h>
#include <math.h>
#include <stdint.h>

#define B_  64
#define T_  512
#define IN_ 1024
#define H_  1024
#define L_  5
#define NC  32
#define TPB 256
typedef unsigned long long ull;
using namespace nvcuda;

// smem: 3 ring slots x 4 planes (Wh,Wl,Sh,Sl) x [64][136] halves
#define WPITCH 136
#define PLANE  (64 * WPITCH)          // 8704 halves
#define SLOTH  (4 * PLANE)            // 34816 halves = 69632 B
#define SMEM_BYTES (3 * SLOTH * 2)    // 208896 B
#define PRP 36                        // partial pitch (floats)

__device__ float  g_xw[(size_t)B_ * T_ * 2 * H_];
__device__ float  g_state[2][B_ * H_];
__device__ __half g_w16[2][2][(size_t)L_ * H_ * H_];   // [gate][hi/lo]
__device__ __half g_s16[2][2][B_ * H_];                // [buf][hi/lo]
__device__ unsigned g_arr[32];
__device__ unsigned g_gen[32];

__device__ __forceinline__ void ffma2(ull& d, ull a, ull b) {
    asm("fma.rn.f32x2 %0, %1, %2, %0;" : "+l"(d) : "l"(a), "l"(b));
}
__device__ __forceinline__ ull packff(float x, float y) {
    ull r; asm("mov.b64 %0, {%1, %2};" : "=l"(r) : "f"(x), "f"(y)); return r;
}
__device__ __forceinline__ void cp16(uint32_t dst, const void* src) {
    asm volatile("cp.async.cg.shared.global [%0], [%1], 16;" :: "r"(dst), "l"(src) : "memory");
}
#define CP_COMMIT() asm volatile("cp.async.commit_group;" ::: "memory")
#define CP_WAIT0()  asm volatile("cp.async.wait_group 0;" ::: "memory")
#define CP_WAIT1()  asm volatile("cp.async.wait_group 1;" ::: "memory")

// ---- setup kernels --------------------------------------------------------
__global__ void reset_barrier_kernel() {
    int i = threadIdx.x;
    if (i < 32) { g_arr[i] = 0u; g_gen[i] = 0u; }
}
__global__ void wconvert_kernel(const float* __restrict__ rh_w,
                                const float* __restrict__ rt_w) {
    const size_t n = (size_t)L_ * H_ * H_;
    for (size_t i = (size_t)blockIdx.x * blockDim.x + threadIdx.x; i < n;
         i += (size_t)gridDim.x * blockDim.x) {
        float a = rh_w[i]; __half h = __float2half_rn(a);
        g_w16[0][0][i] = h; g_w16[0][1][i] = __float2half_rn(a - __half2float(h));
        float b = rt_w[i]; __half h2 = __float2half_rn(b);
        g_w16[1][0][i] = h2; g_w16[1][1][i] = __float2half_rn(b - __half2float(h2));
    }
}
__global__ void sinit_kernel(const float* __restrict__ s0) {
    int i = blockIdx.x * blockDim.x + threadIdx.x;
    if (i < B_ * H_) {
        float v = s0[i]; __half h = __float2half_rn(v);
        g_s16[0][0][i] = h; g_s16[0][1][i] = __float2half_rn(v - __half2float(h));
    }
}

// ---- input GEMM (fp32 FFMA2, proven) --------------------------------------
__global__ __launch_bounds__(256) void xw_gemm_kernel(
    const float* __restrict__ x, const float* __restrict__ w_h,
    const float* __restrict__ w_t)
{
    __shared__ float As[8][132];
    __shared__ float Bs[8][132];
    const int jb = blockIdx.x, rb = blockIdx.y, tid = threadIdx.x;
    const int tx = tid % 16, ty = tid / 16;
    const int jbase = jb * 128;
    const float* W = (jbase < H_) ? w_h : w_t;
    const int joff = jbase % H_;
    ull acc2[8][4];
    #pragma unroll
    for (int i = 0; i < 8; i++) { acc2[i][0]=0; acc2[i][1]=0; acc2[i][2]=0; acc2[i][3]=0; }
    const int arow = tid / 2, ak = (tid % 2) * 4;
    const int r = rb * 128 + arow;
    const int xrow = (r % B_) * T_ + (r / B_);
    const float* aptr = x + (size_t)xrow * IN_ + ak;
    const int bk = tid / 32, bj = (tid % 32) * 4;
    const float* bptr = W + (size_t)bk * H_ + joff + bj;
    for (int kt = 0; kt < IN_; kt += 8) {
        float4 av = *(const float4*)(aptr + kt);
        float4 bv = *(const float4*)(bptr + (size_t)kt * H_);
        __syncthreads();
        As[ak+0][arow]=av.x; As[ak+1][arow]=av.y; As[ak+2][arow]=av.z; As[ak+3][arow]=av.w;
        *(float4*)&Bs[bk][bj] = bv;
        __syncthreads();
        #pragma unroll
        for (int k = 0; k < 8; k++) {
            float a[8];
            #pragma unroll
            for (int i = 0; i < 8; i++) a[i] = As[k][ty*8+i];
            ulonglong2 b0 = *(const ulonglong2*)&Bs[k][tx*8];
            ulonglong2 b1 = *(const ulonglong2*)&Bs[k][tx*8+4];
            #pragma unroll
            for (int i = 0; i < 8; i++) {
                ull ap = packff(a[i], a[i]);
                ffma2(acc2[i][0], ap, b0.x); ffma2(acc2[i][1], ap, b0.y);
                ffma2(acc2[i][2], ap, b1.x); ffma2(acc2[i][3], ap, b1.y);
            }
        }
    }
    #pragma unroll
    for (int i = 0; i < 8; i++) {
        int rr = rb * 128 + ty * 8 + i;
        float* cp = g_xw + (size_t)rr * (2*H_) + jbase + tx * 8;
        union { ull u; float2 f; } c0, c1, c2, c3;
        c0.u=acc2[i][0]; c1.u=acc2[i][1]; c2.u=acc2[i][2]; c3.u=acc2[i][3];
        *(float4*)(cp+0) = make_float4(c0.f.x,c0.f.y,c1.f.x,c1.f.y);
        *(float4*)(cp+4) = make_float4(c2.f.x,c2.f.y,c3.f.x,c3.f.y);
    }
}

// ---- fence-free 32-CTA barrier --------------------------------------------
__device__ __forceinline__ void group_sync32(int step)
{
    __syncthreads();
    if (threadIdx.x == 0) {
        unsigned old;
        asm volatile("atom.acq_rel.gpu.global.add.u32 %0, [%1], 1;"
                     : "=r"(old) : "l"(&g_arr[0]) : "memory");
        if (old == (unsigned)(step * NC + NC - 1)) {
            asm volatile("st.release.gpu.global.u32 [%0], %1;"
                         :: "l"(&g_gen[0]), "r"((unsigned)(step + 1)) : "memory");
        } else {
            unsigned cur;
            do { asm volatile("ld.acquire.gpu.global.u32 %0, [%1];"
                              : "=r"(cur) : "l"(&g_gen[0]) : "memory");
            } while (cur <= (unsigned)step);
        }
    }
    __syncthreads();
}

// ---- persistent wmma recurrent kernel -------------------------------------
// 32 CTAs. CTA: 32 g-cols x both gates = 64 weight rows (0-31 h, 32-63 t).
// 8 warps = (wk 0..3 k-split) x (wn 0..1 batch-half). Warp tile m64 x n32.
// fp16 hi/lo split, 3 mma terms, fp32 accum.
__global__ __launch_bounds__(TPB) void rhn_wmma_kernel(
    const float* __restrict__ rh_b, const float* __restrict__ rt_b,
    float* __restrict__ out)
{
    extern __shared__ __half smh[];
    float* pr = (float*)smh;                 // partials alias slots 0-1
    const uint32_t sb = (uint32_t)__cvta_generic_to_shared(smh);

    const int tid  = threadIdx.x;
    const int warp = tid >> 5;
    const int wk   = warp >> 1;              // 0..3 k-split
    const int wn   = warp & 1;               // 0..1 batch half
    const int gb   = blockIdx.x;             // 0..31
    const int gbase = gb * 32;

    // cp.async mapping: 4096 x 16B per tile, 16 per thread
    // idx: plane = idx>>10 (0 Wh,1 Wl,2 Sh,3 Sl), row = (idx>>4)&63, seg = idx&15
    auto issue_tile = [&](int l, int pin, int kt, int slot) {
        #pragma unroll
        for (int i = 0; i < 16; i++) {
            const int idx   = i * 256 + tid;
            const int plane = idx >> 10;
            const int row   = (idx >> 4) & 63;
            const int seg   = idx & 15;
            uint32_t dst = sb + (uint32_t)(slot * SLOTH + plane * PLANE +
                                           row * WPITCH + seg * 8) * 2;
            const __half* src;
            if (plane < 2) {
                const int gate = row >> 5;
                const int g    = gbase + (row & 31);
                src = g_w16[gate][plane] + (size_t)l * H_ * H_ + (size_t)g * H_
                      + kt * 128 + seg * 8;
            } else {
                src = g_s16[pin][plane - 2] + (size_t)row * H_ + kt * 128 + seg * 8;
            }
            cp16(dst, src);
        }
        CP_COMMIT();
    };

    int t = 0, l = 0;
    for (int step = 0; step < T_ * L_; step++) {
        const int pin = step & 1;
        const float* scur = g_state[pin];
        float*       snxt = g_state[pin ^ 1];

        wmma::fragment<wmma::accumulator, 16, 16, 16, float> C[4][2];
        #pragma unroll
        for (int mi = 0; mi < 4; mi++) {
            wmma::fill_fragment(C[mi][0], 0.0f);
            wmma::fill_fragment(C[mi][1], 0.0f);
        }

        issue_tile(l, pin, 0, 0);
        issue_tile(l, pin, 1, 1);

        for (int kt = 0; kt < 8; kt++) {
            if (kt < 7) { CP_WAIT1(); } else { CP_WAIT0(); }
            __syncthreads();
            if (kt < 6) issue_tile(l, pin, kt + 2, (kt + 2) % 3);

            const __half* slot = smh + (kt % 3) * SLOTH;
            #pragma unroll
            for (int ks = 0; ks < 2; ks++) {
                const int koff = (wk * 2 + ks) * 16;
                wmma::fragment<wmma::matrix_b, 16, 16, 16, __half, wmma::col_major> bh[2], bl[2];
                #pragma unroll
                for (int ni = 0; ni < 2; ni++) {
                    const int nrow = wn * 32 + ni * 16;
                    wmma::load_matrix_sync(bh[ni], slot + 2 * PLANE + nrow * WPITCH + koff, WPITCH);
                    wmma::load_matrix_sync(bl[ni], slot + 3 * PLANE + nrow * WPITCH + koff, WPITCH);
                }
                #pragma unroll
                for (int mi = 0; mi < 4; mi++) {
                    wmma::fragment<wmma::matrix_a, 16, 16, 16, __half, wmma::row_major> ah, al;
                    wmma::load_matrix_sync(ah, slot + (mi * 16) * WPITCH + koff, WPITCH);
                    wmma::load_matrix_sync(al, slot + PLANE + (mi * 16) * WPITCH + koff, WPITCH);
                    #pragma unroll
                    for (int ni = 0; ni < 2; ni++) {
                        wmma::mma_sync(C[mi][ni], ah, bh[ni], C[mi][ni]);
                        wmma::mma_sync(C[mi][ni], ah, bl[ni], C[mi][ni]);
                        wmma::mma_sync(C[mi][ni], al, bh[ni], C[mi][ni]);
                    }
                }
            }
        }

        // ---- store k-split partials (alias slots 0-1) ----------------------
        __syncthreads();
        {
            float* base = pr + (size_t)(wn * 4 + wk) * 64 * PRP;
            #pragma unroll
            for (int mi = 0; mi < 4; mi++)
                #pragma unroll
                for (int ni = 0; ni < 2; ni++)
                    wmma::store_matrix_sync(base + mi * 16 * PRP + ni * 16,
                                            C[mi][ni], PRP, wmma::mem_row_major);
        }
        __syncthreads();

        // ---- reduce + fused epilogue: 8 outputs per thread -----------------
        {
            const int gl = tid & 31;
            const int b8 = tid >> 5;
            const int g  = gbase + gl;
            const float bhb = rh_b[l * H_ + g];
            const float btb = rt_b[l * H_ + g];
            #pragma unroll
            for (int i = 0; i < 8; i++) {
                const int b  = b8 * 8 + i;
                const int w2 = b >> 5;
                const int nn = b & 31;
                float ph = bhb, pt = btb;
                #pragma unroll
                for (int k2 = 0; k2 < 4; k2++) {
                    const float* blk = pr + (size_t)(w2 * 4 + k2) * 64 * PRP;
                    ph += blk[gl * PRP + nn];
                    pt += blk[(32 + gl) * PRP + nn];
                }
                if (l == 0) {
                    const float* xw = g_xw + (size_t)(t * B_ + b) * (2 * H_);
                    ph += xw[g]; pt += xw[H_ + g];
                }
                const float so = __ldcg(&scur[(size_t)b * H_ + g]);
                const float hh = tanhf(ph);
                const float tg = 1.0f / (1.0f + expf(-pt));
                const float sn = fmaf(hh - so, tg, so);
                __stcg(&snxt[(size_t)b * H_ + g], sn);
                const __half hi = __float2half_rn(sn);
                const __half lo = __float2half_rn(sn - __half2float(hi));
                const size_t si = (size_t)b * H_ + g;
                unsigned short uhi = __half_as_ushort(hi), ulo = __half_as_ushort(lo);
                asm volatile("st.global.cg.u16 [%0], %1;" :: "l"(&g_s16[pin ^ 1][0][si]), "h"(uhi));
                asm volatile("st.global.cg.u16 [%0], %1;" :: "l"(&g_s16[pin ^ 1][1][si]), "h"(ulo));
                if (l == L_ - 1) {
                    out[((size_t)b * T_ + t) * H_ + g] = sn;
                    if (t == T_ - 1)
                        out[(size_t)B_ * T_ * H_ + (size_t)b * H_ + g] = sn;
                }
            }
        }

        if (++l == L_) { l = 0; ++t; }
        if (step != T_ * L_ - 1) group_sync32(step);
    }
}

// ---------------------------------------------------------------------------
extern "C" void kernel_launch(void* const* d_in, const int* in_sizes, int n_in,
                              void* d_out, int out_size)
{
    const float* input = (const float*)d_in[0];
    const float* s0    = (const float*)d_in[1];
    const float* w_h   = (const float*)d_in[2];
    const float* w_t   = (const float*)d_in[3];
    const float* rh_w  = (const float*)d_in[4];
    const float* rh_b  = (const float*)d_in[5];
    const float* rt_w  = (const float*)d_in[6];
    const float* rt_b  = (const float*)d_in[7];
    float* out = (float*)d_out;

    static bool attr_set = false;
    if (!attr_set) {
        cudaFuncSetAttribute(rhn_wmma_kernel,
                             cudaFuncAttributeMaxDynamicSharedMemorySize, SMEM_BYTES);
        attr_set = true;
    }

    reset_barrier_kernel<<<1, 32>>>();
    cudaMemcpyToSymbolAsync(g_state, s0, (size_t)B_ * H_ * sizeof(float), 0,
                            cudaMemcpyDeviceToDevice);
    sinit_kernel<<<(B_ * H_ + 255) / 256, 256>>>(s0);
    wconvert_kernel<<<2048, 256>>>(rh_w, rt_w);
    {
        dim3 grid(16, 256);
        xw_gemm_kernel<<<grid, 256>>>(input, w_h, w_t);
    }
    rhn_wmma_kernel<<<NC, TPB, SMEM_BYTES>>>(rh_b, rt_b, out);
}

// round 11
// speedup vs baseline: 1.9421x; 1.9421x over previous
#include <cuda_runtime.h>
#include <cuda_fp16.h>
#include <mma.h>
#include <math.h>
#include <stdint.h>

#define B_  64
#define T_  512
#define IN_ 1024
#define H_  1024
#define L_  5
#define NC   128
#define TPB  256
#define NGRP 4
#define CPG  32
#define BPG  16
typedef unsigned long long ull;
using namespace nvcuda;

// smem (halves): 3 ring slots x 160 rows x 136 halves
//   rows 0-63 Whi, 64-127 Wlo, 128-143 Shi, 144-159 Slo
#define WPITCH 136
#define SLOT_H (160 * WPITCH)                 // 21760 halves = 43520 B
#define PART_F (3 * SLOT_H / 2)               // float offset of partials
#define PRP 18
#define SMEM_BYTES (3 * SLOT_H * 2 + 8 * 64 * PRP * 4)   // 130560 + 36864 = 167424

__device__ float  g_xw[(size_t)B_ * T_ * 2 * H_];
__device__ float  g_state[2][B_ * H_];
__device__ __half g_w16[2][2][(size_t)L_ * H_ * H_];   // [gate][hi/lo]
__device__ __half g_s16[2][2][B_ * H_];                // [buf][hi/lo]
__device__ unsigned g_arr[NGRP * 64];
__device__ unsigned g_gen[NGRP * 64];

__device__ __forceinline__ void ffma2(ull& d, ull a, ull b) {
    asm("fma.rn.f32x2 %0, %1, %2, %0;" : "+l"(d) : "l"(a), "l"(b));
}
__device__ __forceinline__ ull packff(float x, float y) {
    ull r; asm("mov.b64 %0, {%1, %2};" : "=l"(r) : "f"(x), "f"(y)); return r;
}
__device__ __forceinline__ void cp16(uint32_t dst, const void* src) {
    asm volatile("cp.async.cg.shared.global [%0], [%1], 16;" :: "r"(dst), "l"(src) : "memory");
}
#define CP_COMMIT() asm volatile("cp.async.commit_group;" ::: "memory")
#define CP_WAIT0()  asm volatile("cp.async.wait_group 0;" ::: "memory")
#define CP_WAIT1()  asm volatile("cp.async.wait_group 1;" ::: "memory")

// ---- setup ----------------------------------------------------------------
__global__ void reset_barrier_kernel() {
    int i = threadIdx.x;
    if (i < NGRP * 64) { g_arr[i] = 0u; g_gen[i] = 0u; }
}
__global__ void wconvert_kernel(const float* __restrict__ rh_w,
                                const float* __restrict__ rt_w) {
    const size_t n = (size_t)L_ * H_ * H_;
    for (size_t i = (size_t)blockIdx.x * blockDim.x + threadIdx.x; i < n;
         i += (size_t)gridDim.x * blockDim.x) {
        float a = rh_w[i]; __half h = __float2half_rn(a);
        g_w16[0][0][i] = h; g_w16[0][1][i] = __float2half_rn(a - __half2float(h));
        float b = rt_w[i]; __half h2 = __float2half_rn(b);
        g_w16[1][0][i] = h2; g_w16[1][1][i] = __float2half_rn(b - __half2float(h2));
    }
}
__global__ void sinit_kernel(const float* __restrict__ s0) {
    int i = blockIdx.x * blockDim.x + threadIdx.x;
    if (i < B_ * H_) {
        float v = s0[i]; __half h = __float2half_rn(v);
        g_s16[0][0][i] = h; g_s16[0][1][i] = __float2half_rn(v - __half2float(h));
    }
}

// ---- input GEMM (fp32 FFMA2, proven) --------------------------------------
__global__ __launch_bounds__(256) void xw_gemm_kernel(
    const float* __restrict__ x, const float* __restrict__ w_h,
    const float* __restrict__ w_t)
{
    __shared__ float As[8][132];
    __shared__ float Bs[8][132];
    const int jb = blockIdx.x, rb = blockIdx.y, tid = threadIdx.x;
    const int tx = tid % 16, ty = tid / 16;
    const int jbase = jb * 128;
    const float* W = (jbase < H_) ? w_h : w_t;
    const int joff = jbase % H_;
    ull acc2[8][4];
    #pragma unroll
    for (int i = 0; i < 8; i++) { acc2[i][0]=0; acc2[i][1]=0; acc2[i][2]=0; acc2[i][3]=0; }
    const int arow = tid / 2, ak = (tid % 2) * 4;
    const int r = rb * 128 + arow;
    const int xrow = (r % B_) * T_ + (r / B_);
    const float* aptr = x + (size_t)xrow * IN_ + ak;
    const int bk = tid / 32, bj = (tid % 32) * 4;
    const float* bptr = W + (size_t)bk * H_ + joff + bj;
    for (int kt = 0; kt < IN_; kt += 8) {
        float4 av = *(const float4*)(aptr + kt);
        float4 bv = *(const float4*)(bptr + (size_t)kt * H_);
        __syncthreads();
        As[ak+0][arow]=av.x; As[ak+1][arow]=av.y; As[ak+2][arow]=av.z; As[ak+3][arow]=av.w;
        *(float4*)&Bs[bk][bj] = bv;
        __syncthreads();
        #pragma unroll
        for (int k = 0; k < 8; k++) {
            float a[8];
            #pragma unroll
            for (int i = 0; i < 8; i++) a[i] = As[k][ty*8+i];
            ulonglong2 b0 = *(const ulonglong2*)&Bs[k][tx*8];
            ulonglong2 b1 = *(const ulonglong2*)&Bs[k][tx*8+4];
            #pragma unroll
            for (int i = 0; i < 8; i++) {
                ull ap = packff(a[i], a[i]);
                ffma2(acc2[i][0], ap, b0.x); ffma2(acc2[i][1], ap, b0.y);
                ffma2(acc2[i][2], ap, b1.x); ffma2(acc2[i][3], ap, b1.y);
            }
        }
    }
    #pragma unroll
    for (int i = 0; i < 8; i++) {
        int rr = rb * 128 + ty * 8 + i;
        float* cp = g_xw + (size_t)rr * (2*H_) + jbase + tx * 8;
        union { ull u; float2 f; } c0, c1, c2, c3;
        c0.u=acc2[i][0]; c1.u=acc2[i][1]; c2.u=acc2[i][2]; c3.u=acc2[i][3];
        *(float4*)(cp+0) = make_float4(c0.f.x,c0.f.y,c1.f.x,c1.f.y);
        *(float4*)(cp+4) = make_float4(c2.f.x,c2.f.y,c3.f.x,c3.f.y);
    }
}

// ---- fence-free scoped barrier (R7) ---------------------------------------
__device__ __forceinline__ void group_sync(int gr, int step)
{
    __syncthreads();
    if (threadIdx.x == 0) {
        unsigned* arr = &g_arr[gr * 64];
        unsigned* gen = &g_gen[gr * 64];
        unsigned old;
        asm volatile("atom.acq_rel.gpu.global.add.u32 %0, [%1], 1;"
                     : "=r"(old) : "l"(arr) : "memory");
        if (old == (unsigned)(step * CPG + CPG - 1)) {
            asm volatile("st.release.gpu.global.u32 [%0], %1;"
                         :: "l"(gen), "r"((unsigned)(step + 1)) : "memory");
        } else {
            unsigned cur;
            do { asm volatile("ld.acquire.gpu.global.u32 %0, [%1];"
                              : "=r"(cur) : "l"(gen) : "memory");
            } while (cur <= (unsigned)step);
        }
    }
    __syncthreads();
}

// ---- persistent wmma recurrent kernel -------------------------------------
// 128 CTAs = 4 groups x 32. CTA: 16 b x 64 gate-rows (32 g-cols, both gates).
// 8 warps k-split-8 within each 128-k tile; warp tile m64 x n16, 3 mma terms.
__global__ __launch_bounds__(TPB, 1) void rhn_wmma_kernel(
    const float* __restrict__ rh_b, const float* __restrict__ rt_b,
    float* __restrict__ out)
{
    extern __shared__ __half smh[];
    float* pr = (float*)smh + PART_F;
    const uint32_t sb = (uint32_t)__cvta_generic_to_shared(smh);

    const int tid  = threadIdx.x;
    const int wk   = tid >> 5;                 // warp = k-split 0..7
    const int gb   = blockIdx.x;
    const int gr   = gb >> 5;
    const int c32  = gb & 31;
    const int bbase = gr * BPG;
    const int gbase = c32 * 32;

    // copy mappings
    const int crow = tid >> 1;                 // for weights: 2 thr/row pattern below
    (void)crow;

    auto issue_w = [&](int l, int kt, int slot) {   // rows 0-127, 8 segs/thread
        #pragma unroll
        for (int i = 0; i < 8; i++) {
            const int idx = i * 256 + tid;
            const int row = idx >> 4;          // 0..127
            const int seg = idx & 15;
            const int plane = row >> 6;
            const int r = row & 63;
            const int gate = r >> 5;
            const int g = gbase + (r & 31);
            const __half* src = g_w16[gate][plane] + (size_t)l * H_ * H_
                                + (size_t)g * H_ + kt * 128 + seg * 8;
            cp16(sb + (uint32_t)(slot * SLOT_H + row * WPITCH + seg * 8) * 2, src);
        }
    };
    auto issue_s = [&](int pin, int kt, int slot) { // rows 128-159, 2 segs/thread
        #pragma unroll
        for (int i = 0; i < 2; i++) {
            const int idx = i * 256 + tid;
            const int rr  = idx >> 4;          // 0..31
            const int seg = idx & 15;
            const int plane = rr >> 4;
            const int b = bbase + (rr & 15);
            const __half* src = g_s16[pin][plane] + (size_t)b * H_ + kt * 128 + seg * 8;
            cp16(sb + (uint32_t)(slot * SLOT_H + (128 + rr) * WPITCH + seg * 8) * 2, src);
        }
    };

    // prologue: step-0 tiles
    issue_w(0, 0, 0); CP_COMMIT();             // A
    issue_s(0, 0, 0); CP_COMMIT();             // B
    issue_w(0, 1, 1); issue_s(0, 1, 1); CP_COMMIT();   // C

    int t = 0, l = 0;
    for (int step = 0; step < T_ * L_; step++) {
        const int pin = step & 1;
        const float* scur = g_state[pin];
        float*       snxt = g_state[pin ^ 1];

        // hoisted epilogue operands (hide L2 latency behind mainloop)
        const int gl  = tid >> 3;              // 0..31
        const int bl0 = (tid & 7) * 2;
        const int bl1 = bl0 + 1;
        const int g   = gbase + gl;
        const int b0g = bbase + bl0;
        const int b1g = bbase + bl1;
        const float bhb = rh_b[l * H_ + g];
        const float btb = rt_b[l * H_ + g];
        const float so0 = __ldcg(&scur[(size_t)b0g * H_ + g]);
        const float so1 = __ldcg(&scur[(size_t)b1g * H_ + g]);
        float xh0 = 0.f, xt0 = 0.f, xh1 = 0.f, xt1 = 0.f;
        if (l == 0) {
            const float* xw0 = g_xw + (size_t)(t * B_ + b0g) * (2 * H_);
            const float* xw1 = g_xw + (size_t)(t * B_ + b1g) * (2 * H_);
            xh0 = xw0[g]; xt0 = xw0[H_ + g];
            xh1 = xw1[g]; xt1 = xw1[H_ + g];
        }

        wmma::fragment<wmma::accumulator, 16, 16, 16, float> C[4];
        #pragma unroll
        for (int mi = 0; mi < 4; mi++) wmma::fill_fragment(C[mi], 0.0f);

        const int koff = wk * 16;
        for (int kt = 0; kt < 8; kt++) {
            if (kt < 7) { CP_WAIT1(); } else { CP_WAIT0(); }
            __syncthreads();
            if (kt < 6) { issue_w(l, kt + 2, (kt + 2) % 3); issue_s(pin, kt + 2, (kt + 2) % 3); CP_COMMIT(); }

            const __half* slot = smh + (kt % 3) * SLOT_H;
            wmma::fragment<wmma::matrix_b, 16, 16, 16, __half, wmma::col_major> bh, blo;
            wmma::load_matrix_sync(bh,  slot + 128 * WPITCH + koff, WPITCH);
            wmma::load_matrix_sync(blo, slot + 144 * WPITCH + koff, WPITCH);
            #pragma unroll
            for (int mi = 0; mi < 4; mi++) {
                wmma::fragment<wmma::matrix_a, 16, 16, 16, __half, wmma::row_major> ah, al;
                wmma::load_matrix_sync(ah, slot + (mi * 16) * WPITCH + koff, WPITCH);
                wmma::load_matrix_sync(al, slot + ((64 + mi * 16)) * WPITCH + koff, WPITCH);
                wmma::mma_sync(C[mi], ah, bh,  C[mi]);
                wmma::mma_sync(C[mi], ah, blo, C[mi]);
                wmma::mma_sync(C[mi], al, bh,  C[mi]);
            }
        }

        // partials (dedicated region)
        {
            float* base = pr + (size_t)wk * 64 * PRP;
            #pragma unroll
            for (int mi = 0; mi < 4; mi++)
                wmma::store_matrix_sync(base + mi * 16 * PRP, C[mi], PRP,
                                        wmma::mem_row_major);
        }
        __syncthreads();

        // reduce + fused epilogue: 2 outputs per thread
        {
            float ph0 = bhb + xh0, pt0 = btb + xt0;
            float ph1 = bhb + xh1, pt1 = btb + xt1;
            #pragma unroll
            for (int w = 0; w < 8; w++) {
                const float* bk_ = pr + (size_t)w * 64 * PRP;
                ph0 += bk_[gl * PRP + bl0];
                pt0 += bk_[(32 + gl) * PRP + bl0];
                ph1 += bk_[gl * PRP + bl1];
                pt1 += bk_[(32 + gl) * PRP + bl1];
            }
            const float h0 = tanhf(ph0), h1 = tanhf(ph1);
            const float tg0 = 1.0f / (1.0f + expf(-pt0));
            const float tg1 = 1.0f / (1.0f + expf(-pt1));
            const float sn0 = fmaf(h0 - so0, tg0, so0);
            const float sn1 = fmaf(h1 - so1, tg1, so1);
            __stcg(&snxt[(size_t)b0g * H_ + g], sn0);
            __stcg(&snxt[(size_t)b1g * H_ + g], sn1);
            const __half h0h = __float2half_rn(sn0);
            const __half h0l = __float2half_rn(sn0 - __half2float(h0h));
            const __half h1h = __float2half_rn(sn1);
            const __half h1l = __float2half_rn(sn1 - __half2float(h1h));
            const size_t si0 = (size_t)b0g * H_ + g;
            const size_t si1 = (size_t)b1g * H_ + g;
            unsigned short u;
            u = __half_as_ushort(h0h);
            asm volatile("st.global.cg.u16 [%0], %1;" :: "l"(&g_s16[pin ^ 1][0][si0]), "h"(u));
            u = __half_as_ushort(h0l);
            asm volatile("st.global.cg.u16 [%0], %1;" :: "l"(&g_s16[pin ^ 1][1][si0]), "h"(u));
            u = __half_as_ushort(h1h);
            asm volatile("st.global.cg.u16 [%0], %1;" :: "l"(&g_s16[pin ^ 1][0][si1]), "h"(u));
            u = __half_as_ushort(h1l);
            asm volatile("st.global.cg.u16 [%0], %1;" :: "l"(&g_s16[pin ^ 1][1][si1]), "h"(u));
            if (l == L_ - 1) {
                out[((size_t)b0g * T_ + t) * H_ + g] = sn0;
                out[((size_t)b1g * T_ + t) * H_ + g] = sn1;
                if (t == T_ - 1) {
                    out[(size_t)B_ * T_ * H_ + (size_t)b0g * H_ + g] = sn0;
                    out[(size_t)B_ * T_ * H_ + (size_t)b1g * H_ + g] = sn1;
                }
            }
        }

        int tn = t, ln = l + 1;
        if (ln == L_) { ln = 0; tn = t + 1; }
        const bool last = (step == T_ * L_ - 1);
        if (!last) {
            issue_w(ln, 0, 0); CP_COMMIT();              // A' (weights: read-only)
            group_sync(gr, step);
            issue_s(pin ^ 1, 0, 0); CP_COMMIT();         // B'
            issue_w(ln, 1, 1); issue_s(pin ^ 1, 1, 1); CP_COMMIT();  // C'
        }
        t = tn; l = ln;
    }
}

// ---------------------------------------------------------------------------
extern "C" void kernel_launch(void* const* d_in, const int* in_sizes, int n_in,
                              void* d_out, int out_size)
{
    const float* input = (const float*)d_in[0];
    const float* s0    = (const float*)d_in[1];
    const float* w_h   = (const float*)d_in[2];
    const float* w_t   = (const float*)d_in[3];
    const float* rh_w  = (const float*)d_in[4];
    const float* rh_b  = (const float*)d_in[5];
    const float* rt_w  = (const float*)d_in[6];
    const float* rt_b  = (const float*)d_in[7];
    float* out = (float*)d_out;

    static bool attr_set = false;
    if (!attr_set) {
        cudaFuncSetAttribute(rhn_wmma_kernel,
                             cudaFuncAttributeMaxDynamicSharedMemorySize, SMEM_BYTES);
        attr_set = true;
    }

    reset_barrier_kernel<<<1, 256>>>();
    cudaMemcpyToSymbolAsync(g_state, s0, (size_t)B_ * H_ * sizeof(float), 0,
                            cudaMemcpyDeviceToDevice);
    sinit_kernel<<<(B_ * H_ + 255) / 256, 256>>>(s0);
    wconvert_kernel<<<2048, 256>>>(rh_w, rt_w);
    {
        dim3 grid(16, 256);
        xw_gemm_kernel<<<grid, 256>>>(input, w_h, w_t);
    }
    rhn_wmma_kernel<<<NC, TPB, SMEM_BYTES>>>(rh_b, rt_b, out);
}

// round 12
// speedup vs baseline: 2.2439x; 1.1554x over previous
#include <cuda_runtime.h>
#include <cuda_fp16.h>
#include <mma.h>
#include <math.h>
#include <stdint.h>

#define B_  64
#define T_  512
#define IN_ 1024
#define H_  1024
#define L_  5
#define NC   128
#define TPB  256
#define NGRP 2
#define CPG  64
#define BPG  32
typedef unsigned long long ull;
using namespace nvcuda;

// recurrent smem (halves): 3 slots x 128 rows x 136
//  rows 0-31 Whi, 32-63 Wlo, 64-95 Shi, 96-127 Slo
#define WPITCH 136
#define SLOT_H (128 * WPITCH)                 // 17408 halves = 34816 B
#define PART_F (3 * SLOT_H / 2)               // float offset of partials
#define PRP 36
#define SMEM_BYTES (3 * SLOT_H * 2 + 8 * 32 * PRP * 4)  // 104448+36864 = 141312

__device__ float  g_xw[(size_t)B_ * T_ * 2 * H_];
__device__ float  g_state[2][B_ * H_];
__device__ __half g_w16[2][2][(size_t)L_ * H_ * H_];   // recurrent W [gate][hi/lo]
__device__ __half g_s16[2][2][B_ * H_];                // state [buf][hi/lo]
__device__ __half g_x16[2][(size_t)B_ * T_ * IN_];     // input  [hi/lo]
__device__ __half g_iw16[2][2][(size_t)IN_ * H_];      // input W [gate][hi/lo], k-major
__device__ unsigned g_arr[NGRP * 64];
__device__ unsigned g_gen[NGRP * 64];

__device__ __forceinline__ void cp16(uint32_t dst, const void* src) {
    asm volatile("cp.async.cg.shared.global [%0], [%1], 16;" :: "r"(dst), "l"(src) : "memory");
}
#define CP_COMMIT() asm volatile("cp.async.commit_group;" ::: "memory")
#define CP_WAIT0()  asm volatile("cp.async.wait_group 0;" ::: "memory")
#define CP_WAIT1()  asm volatile("cp.async.wait_group 1;" ::: "memory")

// ---- setup ----------------------------------------------------------------
__global__ void reset_barrier_kernel() {
    int i = threadIdx.x;
    if (i < NGRP * 64) { g_arr[i] = 0u; g_gen[i] = 0u; }
}
__global__ void wconvert_kernel(const float* __restrict__ rh_w,
                                const float* __restrict__ rt_w) {
    const size_t n = (size_t)L_ * H_ * H_;
    for (size_t i = (size_t)blockIdx.x * blockDim.x + threadIdx.x; i < n;
         i += (size_t)gridDim.x * blockDim.x) {
        float a = rh_w[i]; __half h = __float2half_rn(a);
        g_w16[0][0][i] = h; g_w16[0][1][i] = __float2half_rn(a - __half2float(h));
        float b = rt_w[i]; __half h2 = __float2half_rn(b);
        g_w16[1][0][i] = h2; g_w16[1][1][i] = __float2half_rn(b - __half2float(h2));
    }
}
__global__ void iwconvert_kernel(const float* __restrict__ w_h,
                                 const float* __restrict__ w_t) {
    const size_t n = (size_t)IN_ * H_;
    for (size_t i = (size_t)blockIdx.x * blockDim.x + threadIdx.x; i < n;
         i += (size_t)gridDim.x * blockDim.x) {
        float a = w_h[i]; __half h = __float2half_rn(a);
        g_iw16[0][0][i] = h; g_iw16[0][1][i] = __float2half_rn(a - __half2float(h));
        float b = w_t[i]; __half h2 = __float2half_rn(b);
        g_iw16[1][0][i] = h2; g_iw16[1][1][i] = __float2half_rn(b - __half2float(h2));
    }
}
__global__ void xconvert_kernel(const float* __restrict__ x) {
    const size_t n = (size_t)B_ * T_ * IN_;
    for (size_t i = (size_t)blockIdx.x * blockDim.x + threadIdx.x; i < n;
         i += (size_t)gridDim.x * blockDim.x) {
        float v = x[i]; __half h = __float2half_rn(v);
        g_x16[0][i] = h; g_x16[1][i] = __float2half_rn(v - __half2float(h));
    }
}
__global__ void sinit_kernel(const float* __restrict__ s0) {
    int i = blockIdx.x * blockDim.x + threadIdx.x;
    if (i < B_ * H_) {
        float v = s0[i]; __half h = __float2half_rn(v);
        g_s16[0][0][i] = h; g_s16[0][1][i] = __float2half_rn(v - __half2float(h));
    }
}

// ---- input GEMM via wmma fp16-split ---------------------------------------
// C[r][j] = sum_k X[r][k] * W[k][j], r = t*B+b (x row = b*T+t), j gate-concat.
// CTA 128r x 128j, 8 warps (4 x 2), warp m32 x n64; k-tiles of 32.
#define XA_P 40
#define XB_P 136
__global__ __launch_bounds__(256) void xw_wmma_kernel()
{
    __shared__ __half As[2][128][XA_P];    // [plane][r][k]
    __shared__ __half Bs[2][32][XB_P];     // [plane][k][j]
    const uint32_t sbA = (uint32_t)__cvta_generic_to_shared(&As[0][0][0]);
    const uint32_t sbB = (uint32_t)__cvta_generic_to_shared(&Bs[0][0][0]);

    const int tid = threadIdx.x;
    const int warp = tid >> 5;
    const int wr = warp >> 1;              // 0..3
    const int wc = warp & 1;               // 0..1
    const int rb = blockIdx.y;             // 0..255
    const int jbase = blockIdx.x * 128;    // 0..15 -> j block
    const int gate = jbase >> 10;
    const int joff = jbase & 1023;

    wmma::fragment<wmma::accumulator, 16, 16, 16, float> C[2][4];
    #pragma unroll
    for (int mi = 0; mi < 2; mi++)
        #pragma unroll
        for (int ni = 0; ni < 4; ni++) wmma::fill_fragment(C[mi][ni], 0.0f);

    for (int kt = 0; kt < 32; kt++) {
        __syncthreads();
        // A: 128 r x 32 k x 2 planes; 4 cp16/thread
        #pragma unroll
        for (int i = 0; i < 2; i++) {
            const int idx = i * 256 + tid;        // 0..511
            const int plane = idx >> 8;
            const int r = (idx & 255) >> 1;
            const int seg = idx & 1;              // 16 halves each
            const int rr = rb * 128 + r;
            const int xrow = (rr % B_) * T_ + (rr / B_);
            const __half* src = g_x16[plane] + (size_t)xrow * IN_ + kt * 32 + seg * 16;
            uint32_t dst = sbA + (uint32_t)((plane * 128 + r) * XA_P + seg * 16) * 2;
            cp16(dst, src); cp16(dst + 16, src + 8);
        }
        // B: 32 k x 128 j x 2 planes; 2 cp16/thread
        #pragma unroll
        for (int i = 0; i < 2; i++) {
            const int idx = i * 256 + tid;
            const int plane = idx >> 8;
            const int kr = (idx & 255) >> 3;
            const int seg = idx & 7;
            const __half* src = g_iw16[gate][plane] + (size_t)(kt * 32 + kr) * H_ + joff + seg * 16;
            uint32_t dst = sbB + (uint32_t)((plane * 32 + kr) * XB_P + seg * 16) * 2;
            cp16(dst, src); cp16(dst + 16, src + 8);
        }
        CP_COMMIT(); CP_WAIT0();
        __syncthreads();

        #pragma unroll
        for (int ks = 0; ks < 2; ks++) {
            const int ko = ks * 16;
            wmma::fragment<wmma::matrix_a, 16, 16, 16, __half, wmma::row_major> ah[2], al[2];
            wmma::fragment<wmma::matrix_b, 16, 16, 16, __half, wmma::row_major> bh[4], bl[4];
            #pragma unroll
            for (int mi = 0; mi < 2; mi++) {
                wmma::load_matrix_sync(ah[mi], &As[0][wr * 32 + mi * 16][ko], XA_P);
                wmma::load_matrix_sync(al[mi], &As[1][wr * 32 + mi * 16][ko], XA_P);
            }
            #pragma unroll
            for (int ni = 0; ni < 4; ni++) {
                wmma::load_matrix_sync(bh[ni], &Bs[0][ko][wc * 64 + ni * 16], XB_P);
                wmma::load_matrix_sync(bl[ni], &Bs[1][ko][wc * 64 + ni * 16], XB_P);
            }
            #pragma unroll
            for (int mi = 0; mi < 2; mi++)
                #pragma unroll
                for (int ni = 0; ni < 4; ni++) {
                    wmma::mma_sync(C[mi][ni], ah[mi], bh[ni], C[mi][ni]);
                    wmma::mma_sync(C[mi][ni], ah[mi], bl[ni], C[mi][ni]);
                    wmma::mma_sync(C[mi][ni], al[mi], bh[ni], C[mi][ni]);
                }
        }
    }

    #pragma unroll
    for (int mi = 0; mi < 2; mi++)
        #pragma unroll
        for (int ni = 0; ni < 4; ni++) {
            float* dst = g_xw + (size_t)(rb * 128 + wr * 32 + mi * 16) * (2 * H_)
                         + jbase + wc * 64 + ni * 16;
            wmma::store_matrix_sync(dst, C[mi][ni], 2 * H_, wmma::mem_row_major);
        }
}

// ---- fence-free scoped barrier --------------------------------------------
__device__ __forceinline__ void group_sync(int gr, int step)
{
    __syncthreads();
    if (threadIdx.x == 0) {
        unsigned* arr = &g_arr[gr * 64];
        unsigned* gen = &g_gen[gr * 64];
        unsigned old;
        asm volatile("atom.acq_rel.gpu.global.add.u32 %0, [%1], 1;"
                     : "=r"(old) : "l"(arr) : "memory");
        if (old == (unsigned)(step * CPG + CPG - 1)) {
            asm volatile("st.release.gpu.global.u32 [%0], %1;"
                         :: "l"(gen), "r"((unsigned)(step + 1)) : "memory");
        } else {
            unsigned cur;
            do { asm volatile("ld.acquire.gpu.global.u32 %0, [%1];"
                              : "=r"(cur) : "l"(gen) : "memory");
            } while (cur <= (unsigned)step);
        }
    }
    __syncthreads();
}

// ---- persistent wmma recurrent kernel, NGRP=2 -----------------------------
// 128 CTAs = 2 groups x 64. CTA: 16 g-cols x 2 gates (32 gate-rows) x 32 b.
// 8 warps k-split-8; warp tile m32 x n32, 3 mma terms, ring-3.
__global__ __launch_bounds__(TPB, 1) void rhn_wmma_kernel(
    const float* __restrict__ rh_b, const float* __restrict__ rt_b,
    float* __restrict__ out)
{
    extern __shared__ __half smh[];
    float* pr = (float*)smh + PART_F;
    const uint32_t sb = (uint32_t)__cvta_generic_to_shared(smh);

    const int tid  = threadIdx.x;
    const int wk   = tid >> 5;                 // k-split 0..7
    const int gb   = blockIdx.x;
    const int gr   = gb >> 6;                  // group 0..1
    const int c64  = gb & 63;
    const int bbase = gr * BPG;                // 32 b rows
    const int gbase = c64 * 16;                // 16 g-cols

    auto issue_w = [&](int l, int kt, int slot) {   // rows 0-63: 4 cp16/thread
        #pragma unroll
        for (int i = 0; i < 4; i++) {
            const int idx = i * 256 + tid;
            const int row = idx >> 4;          // 0..63
            const int seg = idx & 15;
            const int plane = row >> 5;
            const int rr = row & 31;
            const int gate = rr >> 4;
            const int g = gbase + (rr & 15);
            const __half* src = g_w16[gate][plane] + (size_t)l * H_ * H_
                                + (size_t)g * H_ + kt * 128 + seg * 8;
            cp16(sb + (uint32_t)(slot * SLOT_H + row * WPITCH + seg * 8) * 2, src);
        }
    };
    auto issue_s = [&](int pin, int kt, int slot) { // rows 64-127: 4 cp16/thread
        #pragma unroll
        for (int i = 0; i < 4; i++) {
            const int idx = i * 256 + tid;
            const int row = idx >> 4;          // 0..63
            const int seg = idx & 15;
            const int plane = row >> 5;
            const int b = bbase + (row & 31);
            const __half* src = g_s16[pin][plane] + (size_t)b * H_ + kt * 128 + seg * 8;
            cp16(sb + (uint32_t)(slot * SLOT_H + (64 + row) * WPITCH + seg * 8) * 2, src);
        }
    };

    // prologue
    issue_w(0, 0, 0); CP_COMMIT();
    issue_s(0, 0, 0); CP_COMMIT();
    issue_w(0, 1, 1); issue_s(0, 1, 1); CP_COMMIT();

    int t = 0, l = 0;
    for (int step = 0; step < T_ * L_; step++) {
        const int pin = step & 1;
        const float* scur = g_state[pin];
        float*       snxt = g_state[pin ^ 1];

        // hoisted epilogue operands: thread -> 2 (g,b) pairs
        const int i0 = tid * 2, i1 = tid * 2 + 1;
        const int gl0 = i0 & 15, bq0 = i0 >> 4;
        const int gl1 = i1 & 15, bq1 = i1 >> 4;
        const int g0 = gbase + gl0, g1 = gbase + gl1;
        const int b0g = bbase + bq0, b1g = bbase + bq1;
        const float bh0 = rh_b[l * H_ + g0], bt0 = rt_b[l * H_ + g0];
        const float bh1 = rh_b[l * H_ + g1], bt1 = rt_b[l * H_ + g1];
        const float so0 = __ldcg(&scur[(size_t)b0g * H_ + g0]);
        const float so1 = __ldcg(&scur[(size_t)b1g * H_ + g1]);
        float xh0 = 0.f, xt0 = 0.f, xh1 = 0.f, xt1 = 0.f;
        if (l == 0) {
            const float* xw0 = g_xw + (size_t)(t * B_ + b0g) * (2 * H_);
            const float* xw1 = g_xw + (size_t)(t * B_ + b1g) * (2 * H_);
            xh0 = xw0[g0]; xt0 = xw0[H_ + g0];
            xh1 = xw1[g1]; xt1 = xw1[H_ + g1];
        }

        wmma::fragment<wmma::accumulator, 16, 16, 16, float> C[2][2];
        #pragma unroll
        for (int mi = 0; mi < 2; mi++) {
            wmma::fill_fragment(C[mi][0], 0.0f);
            wmma::fill_fragment(C[mi][1], 0.0f);
        }

        const int koff = wk * 16;
        for (int kt = 0; kt < 8; kt++) {
            if (kt < 7) { CP_WAIT1(); } else { CP_WAIT0(); }
            __syncthreads();
            if (kt < 6) { issue_w(l, kt + 2, (kt + 2) % 3); issue_s(pin, kt + 2, (kt + 2) % 3); CP_COMMIT(); }

            const __half* slot = smh + (kt % 3) * SLOT_H;
            wmma::fragment<wmma::matrix_b, 16, 16, 16, __half, wmma::col_major> bh[2], bl[2];
            #pragma unroll
            for (int ni = 0; ni < 2; ni++) {
                wmma::load_matrix_sync(bh[ni], slot + (64 + ni * 16) * WPITCH + koff, WPITCH);
                wmma::load_matrix_sync(bl[ni], slot + (96 + ni * 16) * WPITCH + koff, WPITCH);
            }
            #pragma unroll
            for (int mi = 0; mi < 2; mi++) {
                wmma::fragment<wmma::matrix_a, 16, 16, 16, __half, wmma::row_major> ah, al;
                wmma::load_matrix_sync(ah, slot + (mi * 16) * WPITCH + koff, WPITCH);
                wmma::load_matrix_sync(al, slot + (32 + mi * 16) * WPITCH + koff, WPITCH);
                #pragma unroll
                for (int ni = 0; ni < 2; ni++) {
                    wmma::mma_sync(C[mi][ni], ah, bh[ni], C[mi][ni]);
                    wmma::mma_sync(C[mi][ni], ah, bl[ni], C[mi][ni]);
                    wmma::mma_sync(C[mi][ni], al, bh[ni], C[mi][ni]);
                }
            }
        }

        // partials: pr[wk][m 0..31][n 0..31]
        {
            float* base = pr + (size_t)wk * 32 * PRP;
            #pragma unroll
            for (int mi = 0; mi < 2; mi++)
                #pragma unroll
                for (int ni = 0; ni < 2; ni++)
                    wmma::store_matrix_sync(base + mi * 16 * PRP + ni * 16,
                                            C[mi][ni], PRP, wmma::mem_row_major);
        }
        __syncthreads();

        // reduce + fused epilogue (2 outputs/thread)
        {
            float ph0 = bh0 + xh0, pt0 = bt0 + xt0;
            float ph1 = bh1 + xh1, pt1 = bt1 + xt1;
            #pragma unroll
            for (int w = 0; w < 8; w++) {
                const float* bk_ = pr + (size_t)w * 32 * PRP;
                ph0 += bk_[gl0 * PRP + bq0];
                pt0 += bk_[(16 + gl0) * PRP + bq0];
                ph1 += bk_[gl1 * PRP + bq1];
                pt1 += bk_[(16 + gl1) * PRP + bq1];
            }
            const float hh0 = tanhf(ph0), hh1 = tanhf(ph1);
            const float tg0 = 1.0f / (1.0f + expf(-pt0));
            const float tg1 = 1.0f / (1.0f + expf(-pt1));
            const float sn0 = fmaf(hh0 - so0, tg0, so0);
            const float sn1 = fmaf(hh1 - so1, tg1, so1);
            __stcg(&snxt[(size_t)b0g * H_ + g0], sn0);
            __stcg(&snxt[(size_t)b1g * H_ + g1], sn1);
            const __half a0 = __float2half_rn(sn0);
            const __half a1 = __float2half_rn(sn1);
            const __half c0 = __float2half_rn(sn0 - __half2float(a0));
            const __half c1 = __float2half_rn(sn1 - __half2float(a1));
            const size_t si0 = (size_t)b0g * H_ + g0;
            const size_t si1 = (size_t)b1g * H_ + g1;
            unsigned short u;
            u = __half_as_ushort(a0);
            asm volatile("st.global.cg.u16 [%0], %1;" :: "l"(&g_s16[pin ^ 1][0][si0]), "h"(u));
            u = __half_as_ushort(c0);
            asm volatile("st.global.cg.u16 [%0], %1;" :: "l"(&g_s16[pin ^ 1][1][si0]), "h"(u));
            u = __half_as_ushort(a1);
            asm volatile("st.global.cg.u16 [%0], %1;" :: "l"(&g_s16[pin ^ 1][0][si1]), "h"(u));
            u = __half_as_ushort(c1);
            asm volatile("st.global.cg.u16 [%0], %1;" :: "l"(&g_s16[pin ^ 1][1][si1]), "h"(u));
            if (l == L_ - 1) {
                out[((size_t)b0g * T_ + t) * H_ + g0] = sn0;
                out[((size_t)b1g * T_ + t) * H_ + g1] = sn1;
                if (t == T_ - 1) {
                    out[(size_t)B_ * T_ * H_ + (size_t)b0g * H_ + g0] = sn0;
                    out[(size_t)B_ * T_ * H_ + (size_t)b1g * H_ + g1] = sn1;
                }
            }
        }

        int tn = t, ln = l + 1;
        if (ln == L_) { ln = 0; tn = t + 1; }
        const bool last = (step == T_ * L_ - 1);
        if (!last) {
            issue_w(ln, 0, 0); CP_COMMIT();
            group_sync(gr, step);
            issue_s(pin ^ 1, 0, 0); CP_COMMIT();
            issue_w(ln, 1, 1); issue_s(pin ^ 1, 1, 1); CP_COMMIT();
        }
        t = tn; l = ln;
    }
}

// ---------------------------------------------------------------------------
extern "C" void kernel_launch(void* const* d_in, const int* in_sizes, int n_in,
                              void* d_out, int out_size)
{
    const float* input = (const float*)d_in[0];
    const float* s0    = (const float*)d_in[1];
    const float* w_h   = (const float*)d_in[2];
    const float* w_t   = (const float*)d_in[3];
    const float* rh_w  = (const float*)d_in[4];
    const float* rh_b  = (const float*)d_in[5];
    const float* rt_w  = (const float*)d_in[6];
    const float* rt_b  = (const float*)d_in[7];
    float* out = (float*)d_out;

    static bool attr_set = false;
    if (!attr_set) {
        cudaFuncSetAttribute(rhn_wmma_kernel,
                             cudaFuncAttributeMaxDynamicSharedMemorySize, SMEM_BYTES);
        attr_set = true;
    }

    reset_barrier_kernel<<<1, 256>>>();
    cudaMemcpyToSymbolAsync(g_state, s0, (size_t)B_ * H_ * sizeof(float), 0,
                            cudaMemcpyDeviceToDevice);
    sinit_kernel<<<(B_ * H_ + 255) / 256, 256>>>(s0);
    wconvert_kernel<<<2048, 256>>>(rh_w, rt_w);
    iwconvert_kernel<<<1024, 256>>>(w_h, w_t);
    xconvert_kernel<<<4096, 256>>>(input);
    {
        dim3 grid(16, 256);
        xw_wmma_kernel<<<grid, 256>>>();
    }
    rhn_wmma_kernel<<<NC, TPB, SMEM_BYTES>>>(rh_b, rt_b, out);
}